// round 8
// baseline (speedup 1.0000x reference)
#include <cuda_runtime.h>
#include <cuda_bf16.h>
#include <cstdint>

// Problem constants.
constexpr int CDIM = 768;
constexpr int NHD  = 12;
constexpr int HD   = 64;
constexpr int WSZ  = 14;
constexpr int NT   = WSZ * WSZ;        // 196
constexpr int NWIN = 256;
constexpr int M1   = NWIN * NT;        // 50176
constexpr int QKVN = 3 * CDIM;         // 2304

// GEMM tiling: CTA 256x128, K-chunk 32 (bf16), 8 warps (4Mx2N), warp 64x64.
constexpr int KCH = 32;
constexpr int NCH = CDIM / KCH;        // 24
constexpr int NSTG = 2;
// Per-stage smem layout (bytes): A tiles 256 rows x 64B, B tiles 128 x 64B.
constexpr int T_AHI = 0;
constexpr int T_ALO = 16384;
constexpr int T_BHI = 32768;
constexpr int T_BLO = 40960;
constexpr int STG_B = 49152;
constexpr int SMEM_TOT = NSTG * STG_B;  // 96 KB

// Scratch (device globals; runtime allocation is forbidden).
__device__ float g_q[(long)NWIN * NHD * NT * HD];
__device__ float g_k[(long)NWIN * NHD * NT * HD];
__device__ float g_v[(long)NWIN * NHD * NT * HD];
__device__ __nv_bfloat16 g_xhi[(long)M1 * CDIM];
__device__ __nv_bfloat16 g_xlo[(long)M1 * CDIM];
__device__ __nv_bfloat16 g_whi[(long)QKVN * CDIM];
__device__ __nv_bfloat16 g_wlo[(long)QKVN * CDIM];
__device__ __nv_bfloat16 g_pwhi[(long)CDIM * CDIM];
__device__ __nv_bfloat16 g_pwlo[(long)CDIM * CDIM];
__device__ __nv_bfloat16 g_ahi[(long)M1 * CDIM];
__device__ __nv_bfloat16 g_alo[(long)M1 * CDIM];

// ---------------------------------------------------------------------------
// PTX helpers (base-target instructions only; tcgen05 is rejected by ptxas
// on the harness's compute_103 virtual target).
// ---------------------------------------------------------------------------
__device__ __forceinline__ uint32_t smem_u32(const void* p) {
    uint32_t a;
    asm("{ .reg .u64 t; cvta.to.shared.u64 t, %1; cvt.u32.u64 %0, t; }"
        : "=r"(a) : "l"(p));
    return a;
}
__device__ __forceinline__ void cp16(uint32_t dst, const void* src) {
    asm volatile("cp.async.cg.shared.global [%0], [%1], 16;"
                 :: "r"(dst), "l"(src));
}
__device__ __forceinline__ void cp_commit() {
    asm volatile("cp.async.commit_group;");
}
__device__ __forceinline__ void cp_wait1() {
    asm volatile("cp.async.wait_group 1;" ::: "memory");
}
__device__ __forceinline__ void cp_wait0() {
    asm volatile("cp.async.wait_group 0;" ::: "memory");
}
__device__ __forceinline__ void ldsm4(uint32_t* r, uint32_t addr) {
    asm volatile("ldmatrix.sync.aligned.m8n8.x4.shared.b16 {%0,%1,%2,%3}, [%4];"
                 : "=r"(r[0]), "=r"(r[1]), "=r"(r[2]), "=r"(r[3]) : "r"(addr));
}
__device__ __forceinline__ void mma16816(float* d, const uint32_t* a,
                                         uint32_t b0, uint32_t b1) {
    asm volatile(
        "mma.sync.aligned.m16n8k16.row.col.f32.bf16.bf16.f32 "
        "{%0,%1,%2,%3}, {%4,%5,%6,%7}, {%8,%9}, {%0,%1,%2,%3};"
        : "+f"(d[0]), "+f"(d[1]), "+f"(d[2]), "+f"(d[3])
        : "r"(a[0]), "r"(a[1]), "r"(a[2]), "r"(a[3]), "r"(b0), "r"(b1));
}

// 4 floats -> bf16 hi (8B) + bf16 lo (8B).
__device__ __forceinline__ void split4(float4 v, uint2& hi, uint2& lo) {
    __nv_bfloat162 h0 = __floats2bfloat162_rn(v.x, v.y);
    __nv_bfloat162 h1 = __floats2bfloat162_rn(v.z, v.w);
    float2 f0 = __bfloat1622float2(h0);
    float2 f1 = __bfloat1622float2(h1);
    __nv_bfloat162 l0 = __floats2bfloat162_rn(v.x - f0.x, v.y - f0.y);
    __nv_bfloat162 l1 = __floats2bfloat162_rn(v.z - f1.x, v.w - f1.y);
    hi.x = *(uint32_t*)&h0; hi.y = *(uint32_t*)&h1;
    lo.x = *(uint32_t*)&l0; lo.y = *(uint32_t*)&l1;
}

// ---------------------------------------------------------------------------
// Kernel 0: fp32 -> bf16 hi/lo conversion (elementwise).
// ---------------------------------------------------------------------------
__global__ __launch_bounds__(256) void k_cvt(const float* __restrict__ src,
                                            __nv_bfloat16* __restrict__ hi,
                                            __nv_bfloat16* __restrict__ lo,
                                            long n4)
{
    const long i = (long)blockIdx.x * blockDim.x + threadIdx.x;
    if (i >= n4) return;
    float4 v = *(const float4*)(src + i * 4);
    uint2 h, l;
    split4(v, h, l);
    *(uint2*)(hi + i * 4) = h;
    *(uint2*)(lo + i * 4) = l;
}

// ---------------------------------------------------------------------------
// Shared bf16 GEMM mainloop, CTA 256x128, warp 64x64, 3-term split.
// aHiR/aLoR: global row pointers for A tile row = tid (col 0).
// bHiR/bLoR: global row pointers for B tile row = tid>>1 (col 0).
// acc: [4 mf][8 nf][4].
// ---------------------------------------------------------------------------
__device__ __forceinline__ void gemm_main(uint32_t smb,
                                          const __nv_bfloat16* aHiR,
                                          const __nv_bfloat16* aLoR,
                                          const __nv_bfloat16* bHiR,
                                          const __nv_bfloat16* bLoR,
                                          float acc[4][8][4]) {
    const int tid = threadIdx.x;
    const int lane = tid & 31, wid = tid >> 5;

    // --- load geometry ---
    const int arow = tid;                        // A tile row 0..255
    const int aswz = (arow >> 1) & 3;
    const int brow = tid >> 1, bhalf = tid & 1;  // B tile row 0..127, half row
    const int bswz = (brow >> 1) & 3;
    uint32_t adst[4], bdst[2];
#pragma unroll
    for (int c4 = 0; c4 < 4; c4++) adst[c4] = arow * 64 + ((c4 ^ aswz) * 16);
#pragma unroll
    for (int c2 = 0; c2 < 2; c2++) {
        const int bc = bhalf * 2 + c2;
        bdst[c2] = brow * 64 + ((bc ^ bswz) * 16);
    }

    auto issue = [&](int c, int stg) {
        const uint32_t st = smb + stg * STG_B;
        const int kb = c * KCH;
#pragma unroll
        for (int c4 = 0; c4 < 4; c4++) {
            cp16(st + T_AHI + adst[c4], aHiR + kb + c4 * 8);
            cp16(st + T_ALO + adst[c4], aLoR + kb + c4 * 8);
        }
#pragma unroll
        for (int c2 = 0; c2 < 2; c2++) {
            const int bc = bhalf * 2 + c2;
            cp16(st + T_BHI + bdst[c2], bHiR + kb + bc * 8);
            cp16(st + T_BLO + bdst[c2], bLoR + kb + bc * 8);
        }
        cp_commit();
    };

    // --- compute geometry (warp 64x64: 4 M-frags x 4 N16-frags) ---
    const int m_base = (wid & 3) * 64;
    const int n_base = (wid >> 2) * 64;
    const int lr = lane & 15, lh = lane >> 4;
    const uint32_t sw = (lr >> 1) & 3;           // row-swizzle (base mult of 64)
    const uint32_t paS[2] = {((0 + lh) ^ sw) * 16, ((2 + lh) ^ sw) * 16};
    const uint32_t rA64 = (m_base + lr) * 64;
    const uint32_t rB64 = (n_base + lr) * 64;

    issue(0, 0);
    issue(1, 1);
    for (int c = 0; c < NCH; c++) {
        if (c + 1 < NCH) cp_wait1(); else cp_wait0();
        __syncthreads();

        const uint32_t st = smb + (c & 1) * STG_B;
        const uint32_t aHi = st + T_AHI + rA64;
        const uint32_t aLo = st + T_ALO + rA64;
        const uint32_t bHi = st + T_BHI + rB64;
        const uint32_t bLo = st + T_BLO + rB64;

#pragma unroll
        for (int s = 0; s < 2; s++) {
            const uint32_t pa = paS[s];
            uint32_t ah[4][4], al[4][4];
#pragma unroll
            for (int mf = 0; mf < 4; mf++) {
                ldsm4(ah[mf], aHi + mf * 1024 + pa);
                ldsm4(al[mf], aLo + mf * 1024 + pa);
            }
#pragma unroll
            for (int nfp = 0; nfp < 4; nfp++) {
                uint32_t bh[4], bl[4];
                ldsm4(bh, bHi + nfp * 1024 + pa);
                ldsm4(bl, bLo + nfp * 1024 + pa);
#pragma unroll
                for (int mf = 0; mf < 4; mf++)
#pragma unroll
                    for (int q = 0; q < 2; q++) {
                        float* d = acc[mf][nfp * 2 + q];
                        mma16816(d, ah[mf], bh[q], bh[q + 2]);   // hi*hi
                        mma16816(d, ah[mf], bl[q], bl[q + 2]);   // hi*lo
                        mma16816(d, al[mf], bh[q], bh[q + 2]);   // lo*hi
                    }
            }
        }
        __syncthreads();
        if (c + 2 < NCH) issue(c + 2, c & 1);
    }
}

// ---------------------------------------------------------------------------
// Kernel 1: fused window-partition + QKV GEMM (bf16 inputs from g_xhi/lo)
// ---------------------------------------------------------------------------
__global__ __launch_bounds__(256, 1) void k_qkv_mma(
    const float* __restrict__ qb, const float* __restrict__ vb)
{
    extern __shared__ char sm[];
    const uint32_t smb = smem_u32(sm);
    const int tid = threadIdx.x;
    const int lane = tid & 31, wid = tid >> 5;
    const int bn = blockIdx.x, bm = blockIdx.y;
    const int m0 = bm * 256, n0 = bn * 128;

    // A row through the window permutation (bf16 copies of x).
    long aoff;
    {
        const int am = m0 + tid;
        const int wwin = am / NT;
        const int nn = am - wwin * NT;
        const int bimg = wwin >> 4, wi = wwin & 15;
        const int rr = (wi >> 2) * WSZ + nn / WSZ;
        const int cc = (wi & 3) * WSZ + nn % WSZ;
        aoff = ((long)bimg * 3136 + (long)rr * 56 + cc) * CDIM;
    }
    const long boff = (long)(n0 + (tid >> 1)) * CDIM;

    float acc[4][8][4];
#pragma unroll
    for (int a = 0; a < 4; a++)
#pragma unroll
        for (int b = 0; b < 8; b++)
#pragma unroll
            for (int c = 0; c < 4; c++) acc[a][b][c] = 0.f;

    gemm_main(smb, g_xhi + aoff, g_xlo + aoff, g_whi + boff, g_wlo + boff, acc);

    // Epilogue: scatter into q/k/v, [win, head, tok, hd] layout (fp32).
    const int m_base = (wid & 3) * 64, n_base = (wid >> 2) * 64;
    const int qrow = lane >> 2, qcol = (lane & 3) * 2;
    const int part = n0 / CDIM;              // 0:q 1:k 2:v
    const int jrbase = n0 - part * CDIM + n_base;
    const int hh = jrbase >> 6;
    float* dst = (part == 0) ? g_q : (part == 1) ? g_k : g_v;

#pragma unroll
    for (int mf = 0; mf < 4; mf++)
#pragma unroll
        for (int half = 0; half < 2; half++) {
            const int rl = m_base + mf * 16 + half * 8 + qrow;
            const int m = m0 + rl;
            const int w2 = m / NT, n2 = m - w2 * NT;
            float* rp = dst + (long)w2 * (NHD * NT * HD)
                            + ((long)hh * NT + n2) * HD;
#pragma unroll
            for (int nf = 0; nf < 8; nf++) {
                const int dd = nf * 8 + qcol;
                float vx = acc[mf][nf][half * 2 + 0];
                float vy = acc[mf][nf][half * 2 + 1];
                const int jr = jrbase + dd;
                if (part == 0) {
                    vx = (vx + qb[jr]) * 0.125f;
                    vy = (vy + qb[jr + 1]) * 0.125f;
                } else if (part == 2) {
                    vx += vb[jr]; vy += vb[jr + 1];
                }
                *(float2*)(rp + dd) = make_float2(vx, vy);
            }
        }
}

// ---------------------------------------------------------------------------
// Kernel 2: windowed attention (fp32 flash-style, unchanged); emits bf16
// hi/lo pairs directly for the projection GEMM.
// ---------------------------------------------------------------------------
__global__ __launch_bounds__(224) void k_attn(const float* __restrict__ table)
{
    const int w  = blockIdx.x;
    const int h  = blockIdx.y;
    const int tid = threadIdx.x;

    __shared__ float Ks[14][64];
    __shared__ float Vs[14][64];
    __shared__ float tb[729];

    for (int t = tid; t < 729; t += 224) tb[t] = table[t * NHD + h];

    const long base = ((long)w * NHD + h) * NT * HD;
    const int i  = tid;
    const int iy = i / WSZ;
    const int ix = i - iy * WSZ;

    float4 q4[16];
    float4 o4[16];
    float mmax = -1e30f, lsum = 0.f;
    if (i < NT) {
        const float4* qp = (const float4*)(g_q + base + (long)i * HD);
#pragma unroll
        for (int kk = 0; kk < 16; kk++) {
            q4[kk] = qp[kk];
            o4[kk] = make_float4(0.f, 0.f, 0.f, 0.f);
        }
    }
    __syncthreads();

    for (int jt = 0; jt < 14; jt++) {
        const float4* kp = (const float4*)(g_k + base + (long)jt * 14 * HD);
        const float4* vp = (const float4*)(g_v + base + (long)jt * 14 * HD);
        ((float4*)Ks)[tid] = kp[tid];
        ((float4*)Vs)[tid] = vp[tid];
        __syncthreads();

        if (i < NT) {
            float s[14];
            float tmax = -1e30f;
#pragma unroll
            for (int jj = 0; jj < 14; jj++) {
                const float4* kr = (const float4*)Ks[jj];
                float a0 = 0.f, a1 = 0.f, a2 = 0.f, a3 = 0.f;
#pragma unroll
                for (int kk = 0; kk < 16; kk++) {
                    float4 kv = kr[kk];
                    float4 qv = q4[kk];
                    a0 += qv.x * kv.x; a1 += qv.y * kv.y;
                    a2 += qv.z * kv.z; a3 += qv.w * kv.w;
                }
                float sc = (a0 + a1) + (a2 + a3);
                sc += tb[(iy - jt + 13) * 27 + (ix - jj + 13)];
                s[jj] = sc;
                tmax = fmaxf(tmax, sc);
            }
            const float mnew = fmaxf(mmax, tmax);
            const float corr = __expf(mmax - mnew);
            mmax = mnew;
            lsum *= corr;
#pragma unroll
            for (int kk = 0; kk < 16; kk++) {
                o4[kk].x *= corr; o4[kk].y *= corr;
                o4[kk].z *= corr; o4[kk].w *= corr;
            }
#pragma unroll
            for (int jj = 0; jj < 14; jj++) {
                const float p = __expf(s[jj] - mmax);
                lsum += p;
                const float4* vr = (const float4*)Vs[jj];
#pragma unroll
                for (int kk = 0; kk < 16; kk++) {
                    float4 vv = vr[kk];
                    o4[kk].x += p * vv.x; o4[kk].y += p * vv.y;
                    o4[kk].z += p * vv.z; o4[kk].w += p * vv.w;
                }
            }
        }
        __syncthreads();
    }

    if (i < NT) {
        const float inv = 1.f / lsum;
        const int bimg = w >> 4, wi = w & 15;
        const int r = (wi >> 2) * WSZ + iy;
        const int c = (wi & 3) * WSZ + ix;
        const long ob = ((long)bimg * 3136 + (long)r * 56 + c) * CDIM + h * HD;
#pragma unroll
        for (int kk = 0; kk < 16; kk++) {
            float4 t = o4[kk];
            t.x *= inv; t.y *= inv; t.z *= inv; t.w *= inv;
            uint2 hi, lo;
            split4(t, hi, lo);
            *(uint2*)(g_ahi + ob + kk * 4) = hi;
            *(uint2*)(g_alo + ob + kk * 4) = lo;
        }
    }
}

// ---------------------------------------------------------------------------
// Kernel 3: output projection GEMM (bf16 inputs from g_ahi/lo, g_pwhi/lo)
// ---------------------------------------------------------------------------
__global__ __launch_bounds__(256, 1) void k_proj_mma(
    const float* __restrict__ pb, float* __restrict__ out)
{
    extern __shared__ char sm[];
    const uint32_t smb = smem_u32(sm);
    const int tid = threadIdx.x;
    const int lane = tid & 31, wid = tid >> 5;
    const int bn = blockIdx.x, bm = blockIdx.y;
    const int m0 = bm * 256, n0 = bn * 128;

    const long aoff = (long)(m0 + tid) * CDIM;
    const long boff = (long)(n0 + (tid >> 1)) * CDIM;

    float acc[4][8][4];
#pragma unroll
    for (int a = 0; a < 4; a++)
#pragma unroll
        for (int b = 0; b < 8; b++)
#pragma unroll
            for (int c = 0; c < 4; c++) acc[a][b][c] = 0.f;

    gemm_main(smb, g_ahi + aoff, g_alo + aoff, g_pwhi + boff, g_pwlo + boff, acc);

    const int m_base = (wid & 3) * 64, n_base = (wid >> 2) * 64;
    const int qrow = lane >> 2, qcol = (lane & 3) * 2;

#pragma unroll
    for (int mf = 0; mf < 4; mf++)
#pragma unroll
        for (int half = 0; half < 2; half++) {
            const int rl = m_base + mf * 16 + half * 8 + qrow;
            const int m = m0 + rl;
            float* rp = out + (long)m * CDIM + n0 + n_base;
#pragma unroll
            for (int nf = 0; nf < 8; nf++) {
                const int dd = nf * 8 + qcol;
                const float2 bias = *(const float2*)(pb + n0 + n_base + dd);
                *(float2*)(rp + dd) = make_float2(
                    acc[mf][nf][half * 2 + 0] + bias.x,
                    acc[mf][nf][half * 2 + 1] + bias.y);
            }
        }
}

// ---------------------------------------------------------------------------
extern "C" void kernel_launch(void* const* d_in, const int* in_sizes, int n_in,
                              void* d_out, int out_size)
{
    const float* x    = (const float*)d_in[0];
    const float* qkvw = (const float*)d_in[1];
    const float* qb   = (const float*)d_in[2];
    const float* vb   = (const float*)d_in[3];
    const float* tbl  = (const float*)d_in[4];
    const float* pw   = (const float*)d_in[5];
    const float* pb   = (const float*)d_in[6];
    float* out = (float*)d_out;

    cudaFuncSetAttribute(k_qkv_mma,
                         cudaFuncAttributeMaxDynamicSharedMemorySize, SMEM_TOT);
    cudaFuncSetAttribute(k_proj_mma,
                         cudaFuncAttributeMaxDynamicSharedMemorySize, SMEM_TOT);

    __nv_bfloat16 *xhi, *xlo, *whi, *wlo, *pwhi, *pwlo;
    cudaGetSymbolAddress((void**)&xhi, g_xhi);
    cudaGetSymbolAddress((void**)&xlo, g_xlo);
    cudaGetSymbolAddress((void**)&whi, g_whi);
    cudaGetSymbolAddress((void**)&wlo, g_wlo);
    cudaGetSymbolAddress((void**)&pwhi, g_pwhi);
    cudaGetSymbolAddress((void**)&pwlo, g_pwlo);

    // Pre-convert fp32 operands to bf16 hi/lo.
    {
        const long n4x = (long)M1 * CDIM / 4;
        k_cvt<<<(unsigned)((n4x + 255) / 256), 256>>>(x, xhi, xlo, n4x);
        const long n4w = (long)QKVN * CDIM / 4;
        k_cvt<<<(unsigned)((n4w + 255) / 256), 256>>>(qkvw, whi, wlo, n4w);
        const long n4p = (long)CDIM * CDIM / 4;
        k_cvt<<<(unsigned)((n4p + 255) / 256), 256>>>(pw, pwhi, pwlo, n4p);
    }

    dim3 g1(QKVN / 128, M1 / 256);   // (18, 196)
    k_qkv_mma<<<g1, 256, SMEM_TOT>>>(qb, vb);

    dim3 g2(NWIN, NHD);              // (256, 12)
    k_attn<<<g2, 224>>>(tbl);

    dim3 g3(CDIM / 128, M1 / 256);   // (6, 196)
    k_proj_mma<<<g3, 256, SMEM_TOT>>>(pb, out);
}

// round 10
// speedup vs baseline: 1.5808x; 1.5808x over previous
#include <cuda_runtime.h>
#include <cuda_bf16.h>
#include <cstdint>

// Problem constants.
constexpr int CDIM = 768;
constexpr int NHD  = 12;
constexpr int HD   = 64;
constexpr int WSZ  = 14;
constexpr int NT   = WSZ * WSZ;        // 196
constexpr int NWIN = 256;
constexpr int M1   = NWIN * NT;        // 50176
constexpr int QKVN = 3 * CDIM;         // 2304

// Attention padded dims (mma tiles of 16).
constexpr int MP = 224;                // query rows padded (14 x 16)
constexpr int NP = 208;                // key rows padded (13 x 16)

// GEMM tiling (R7 config): CTA 128x128, K-chunk 32, 8 warps (4Mx2N), 3 stages.
constexpr int KCH = 32;
constexpr int NCH = CDIM / KCH;        // 24
constexpr int NSTG = 3;
constexpr int T_AHI = 0;
constexpr int T_ALO = 8192;
constexpr int T_BHI = 16384;
constexpr int T_BLO = 24576;
constexpr int STG_B = 32768;
constexpr int SMEM_TOT = NSTG * STG_B;  // 96 KB

// Attention smem layout (bytes).
constexpr int A_QHI = 0;
constexpr int A_QLO = A_QHI + MP * 128;    // 28672
constexpr int A_KHI = A_QLO + MP * 128;    // 57344
constexpr int A_KLO = A_KHI + NP * 128;    // 83968
constexpr int A_VHI = A_KLO + NP * 128;    // 110592
constexpr int A_VLO = A_VHI + NP * 128;    // 137216
constexpr int A_TB  = A_VLO + NP * 128;    // 163840
constexpr int SMEM_ATT = A_TB + 729 * 4 + 28;  // ~163 KB

// Scratch (device globals; runtime allocation is forbidden; BSS is zero-init,
// so padded rows of q/k/v read as zeros).
__device__ __nv_bfloat16 g_qhi[(long)NWIN * NHD * MP * HD];
__device__ __nv_bfloat16 g_qlo[(long)NWIN * NHD * MP * HD];
__device__ __nv_bfloat16 g_khi[(long)NWIN * NHD * NP * HD];
__device__ __nv_bfloat16 g_klo[(long)NWIN * NHD * NP * HD];
__device__ __nv_bfloat16 g_vhi[(long)NWIN * NHD * NP * HD];
__device__ __nv_bfloat16 g_vlo[(long)NWIN * NHD * NP * HD];
__device__ __nv_bfloat16 g_xhi[(long)M1 * CDIM];
__device__ __nv_bfloat16 g_xlo[(long)M1 * CDIM];
__device__ __nv_bfloat16 g_whi[(long)QKVN * CDIM];
__device__ __nv_bfloat16 g_wlo[(long)QKVN * CDIM];
__device__ __nv_bfloat16 g_pwhi[(long)CDIM * CDIM];
__device__ __nv_bfloat16 g_pwlo[(long)CDIM * CDIM];
__device__ __nv_bfloat16 g_ahi[(long)M1 * CDIM];
__device__ __nv_bfloat16 g_alo[(long)M1 * CDIM];

// ---------------------------------------------------------------------------
// PTX helpers (base-target instructions only; tcgen05 is rejected by ptxas
// on the harness's compute_103 virtual target).
// ---------------------------------------------------------------------------
__device__ __forceinline__ uint32_t smem_u32(const void* p) {
    uint32_t a;
    asm("{ .reg .u64 t; cvta.to.shared.u64 t, %1; cvt.u32.u64 %0, t; }"
        : "=r"(a) : "l"(p));
    return a;
}
__device__ __forceinline__ void cp16(uint32_t dst, const void* src) {
    asm volatile("cp.async.cg.shared.global [%0], [%1], 16;"
                 :: "r"(dst), "l"(src));
}
__device__ __forceinline__ void cp_commit() {
    asm volatile("cp.async.commit_group;");
}
__device__ __forceinline__ void cp_wait1() {
    asm volatile("cp.async.wait_group 1;" ::: "memory");
}
__device__ __forceinline__ void cp_wait0() {
    asm volatile("cp.async.wait_group 0;" ::: "memory");
}
__device__ __forceinline__ void ldsm4(uint32_t* r, uint32_t addr) {
    asm volatile("ldmatrix.sync.aligned.m8n8.x4.shared.b16 {%0,%1,%2,%3}, [%4];"
                 : "=r"(r[0]), "=r"(r[1]), "=r"(r[2]), "=r"(r[3]) : "r"(addr));
}
__device__ __forceinline__ void ldsm4t(uint32_t* r, uint32_t addr) {
    asm volatile("ldmatrix.sync.aligned.m8n8.x4.trans.shared.b16 {%0,%1,%2,%3}, [%4];"
                 : "=r"(r[0]), "=r"(r[1]), "=r"(r[2]), "=r"(r[3]) : "r"(addr));
}
__device__ __forceinline__ void mma16816(float* d, const uint32_t* a,
                                         uint32_t b0, uint32_t b1) {
    asm volatile(
        "mma.sync.aligned.m16n8k16.row.col.f32.bf16.bf16.f32 "
        "{%0,%1,%2,%3}, {%4,%5,%6,%7}, {%8,%9}, {%0,%1,%2,%3};"
        : "+f"(d[0]), "+f"(d[1]), "+f"(d[2]), "+f"(d[3])
        : "r"(a[0]), "r"(a[1]), "r"(a[2]), "r"(a[3]), "r"(b0), "r"(b1));
}

// 2 floats -> bf16x2 hi + bf16x2 lo words.
__device__ __forceinline__ void split2(float x, float y, uint32_t& h, uint32_t& l) {
    __nv_bfloat162 hh = __floats2bfloat162_rn(x, y);
    float2 f = __bfloat1622float2(hh);
    __nv_bfloat162 ll = __floats2bfloat162_rn(x - f.x, y - f.y);
    h = *(uint32_t*)&hh; l = *(uint32_t*)&ll;
}
// 4 floats -> bf16 hi (8B) + bf16 lo (8B).
__device__ __forceinline__ void split4(float4 v, uint2& hi, uint2& lo) {
    split2(v.x, v.y, hi.x, lo.x);
    split2(v.z, v.w, hi.y, lo.y);
}

// ---------------------------------------------------------------------------
// Kernel 0: fp32 -> bf16 hi/lo conversion (elementwise).
// ---------------------------------------------------------------------------
__global__ __launch_bounds__(256) void k_cvt(const float* __restrict__ src,
                                            __nv_bfloat16* __restrict__ hi,
                                            __nv_bfloat16* __restrict__ lo,
                                            long n4)
{
    const long i = (long)blockIdx.x * blockDim.x + threadIdx.x;
    if (i >= n4) return;
    float4 v = *(const float4*)(src + i * 4);
    uint2 h, l;
    split4(v, h, l);
    *(uint2*)(hi + i * 4) = h;
    *(uint2*)(lo + i * 4) = l;
}

// ---------------------------------------------------------------------------
// Shared bf16 GEMM mainloop (R7 exact): CTA 128x128, warp 32x64, 3 stages.
// ---------------------------------------------------------------------------
__device__ __forceinline__ void gemm_main(uint32_t smb,
                                          const __nv_bfloat16* aHiR,
                                          const __nv_bfloat16* aLoR,
                                          const __nv_bfloat16* bHiR,
                                          const __nv_bfloat16* bLoR,
                                          float acc[2][8][4]) {
    const int tid = threadIdx.x;
    const int lane = tid & 31, wid = tid >> 5;
    const int srow = tid >> 1, shalf = tid & 1;
    const int bswz = (srow >> 1) & 3;

    const uint32_t d0 = srow * 64 + (((shalf * 2 + 0) ^ bswz) * 16);
    const uint32_t d1 = srow * 64 + (((shalf * 2 + 1) ^ bswz) * 16);
    const int e0 = (shalf * 2 + 0) * 8;
    const int e1 = (shalf * 2 + 1) * 8;

    auto issue = [&](int c, int stg) {
        const uint32_t st = smb + stg * STG_B;
        const int kb = c * KCH;
        cp16(st + T_AHI + d0, aHiR + kb + e0);
        cp16(st + T_AHI + d1, aHiR + kb + e1);
        cp16(st + T_ALO + d0, aLoR + kb + e0);
        cp16(st + T_ALO + d1, aLoR + kb + e1);
        cp16(st + T_BHI + d0, bHiR + kb + e0);
        cp16(st + T_BHI + d1, bHiR + kb + e1);
        cp16(st + T_BLO + d0, bLoR + kb + e0);
        cp16(st + T_BLO + d1, bLoR + kb + e1);
        cp_commit();
    };

    const int m_base = (wid & 3) * 32;
    const int n_base = (wid >> 2) * 64;
    const int lr = lane & 15, lh = lane >> 4;
    const int rA = m_base + lr;
    const int rB = n_base + lr;
    const uint32_t swA = (rA >> 1) & 3;
    const uint32_t swB = (rB >> 1) & 3;
    const uint32_t paS[2] = {((0 + lh) ^ swA) * 16, ((2 + lh) ^ swA) * 16};
    const uint32_t pbS[2] = {((0 + lh) ^ swB) * 16, ((2 + lh) ^ swB) * 16};
    const uint32_t rA64 = rA * 64, rB64 = rB * 64;

    issue(0, 0);
    issue(1, 1);
    for (int c = 0; c < NCH; c++) {
        const int stg = c % NSTG;
        if (c + 1 < NCH) cp_wait1(); else cp_wait0();
        __syncthreads();
        if (c + 2 < NCH) issue(c + 2, (c + 2) % NSTG);

        const uint32_t st = smb + stg * STG_B;
        const uint32_t aHi = st + T_AHI + rA64;
        const uint32_t aLo = st + T_ALO + rA64;
        const uint32_t bHi = st + T_BHI + rB64;
        const uint32_t bLo = st + T_BLO + rB64;

#pragma unroll
        for (int s = 0; s < 2; s++) {
            const uint32_t pa = paS[s], pb = pbS[s];
            uint32_t ah[2][4], al[2][4];
            ldsm4(ah[0], aHi + pa); ldsm4(ah[1], aHi + 1024 + pa);
            ldsm4(al[0], aLo + pa); ldsm4(al[1], aLo + 1024 + pa);
#pragma unroll
            for (int nfp = 0; nfp < 4; nfp++) {
                uint32_t bh[4], bl[4];
                ldsm4(bh, bHi + nfp * 1024 + pb);
                ldsm4(bl, bLo + nfp * 1024 + pb);
#pragma unroll
                for (int mf = 0; mf < 2; mf++)
#pragma unroll
                    for (int q = 0; q < 2; q++) {
                        float* d = acc[mf][nfp * 2 + q];
                        mma16816(d, ah[mf], bh[q], bh[q + 2]);   // hi*hi
                        mma16816(d, ah[mf], bl[q], bl[q + 2]);   // hi*lo
                        mma16816(d, al[mf], bh[q], bh[q + 2]);   // lo*hi
                    }
            }
        }
    }
}

// ---------------------------------------------------------------------------
// Kernel 1: fused window-partition + QKV GEMM; epilogue writes q/k/v as
// bf16 hi/lo into padded per-(window,head) layouts for the mma attention.
// ---------------------------------------------------------------------------
__global__ __launch_bounds__(256, 2) void k_qkv_mma(
    const float* __restrict__ qb, const float* __restrict__ vb)
{
    extern __shared__ char sm[];
    const uint32_t smb = smem_u32(sm);
    const int tid = threadIdx.x;
    const int lane = tid & 31, wid = tid >> 5;
    const int bn = blockIdx.x, bm = blockIdx.y;
    const int m0 = bm * 128, n0 = bn * 128;

    long aoff;
    {
        const int srow = tid >> 1;
        const int am = m0 + srow;
        const int wwin = am / NT;
        const int nn = am - wwin * NT;
        const int bimg = wwin >> 4, wi = wwin & 15;
        const int rr = (wi >> 2) * WSZ + nn / WSZ;
        const int cc = (wi & 3) * WSZ + nn % WSZ;
        aoff = ((long)bimg * 3136 + (long)rr * 56 + cc) * CDIM;
    }
    const long boff = (long)(n0 + (tid >> 1)) * CDIM;

    float acc[2][8][4];
#pragma unroll
    for (int a = 0; a < 2; a++)
#pragma unroll
        for (int b = 0; b < 8; b++)
#pragma unroll
            for (int c = 0; c < 4; c++) acc[a][b][c] = 0.f;

    gemm_main(smb, g_xhi + aoff, g_xlo + aoff, g_whi + boff, g_wlo + boff, acc);

    // Epilogue: split-bf16 scatter into padded q/k/v.
    const int m_base = (wid & 3) * 32, n_base = (wid >> 2) * 64;
    const int qrow = lane >> 2, qcol = (lane & 3) * 2;
    const int part = n0 / CDIM;              // 0:q 1:k 2:v
    const int jrbase = n0 - part * CDIM + n_base;
    const int hh = jrbase >> 6;
    __nv_bfloat16* dhi = (part == 0) ? g_qhi : (part == 1) ? g_khi : g_vhi;
    __nv_bfloat16* dlo = (part == 0) ? g_qlo : (part == 1) ? g_klo : g_vlo;
    const int rstr = (part == 0) ? MP : NP;

#pragma unroll
    for (int mf = 0; mf < 2; mf++)
#pragma unroll
        for (int half = 0; half < 2; half++) {
            const int rl = m_base + mf * 16 + half * 8 + qrow;
            const int m = m0 + rl;
            const int w2 = m / NT, n2 = m - w2 * NT;
            const long rb = (((long)w2 * NHD + hh) * rstr + n2) * HD;
#pragma unroll
            for (int nf = 0; nf < 8; nf++) {
                const int dd = nf * 8 + qcol;
                float vx = acc[mf][nf][half * 2 + 0];
                float vy = acc[mf][nf][half * 2 + 1];
                const int jr = jrbase + dd;
                if (part == 0) {
                    vx = (vx + qb[jr]) * 0.125f;
                    vy = (vy + qb[jr + 1]) * 0.125f;
                } else if (part == 2) {
                    vx += vb[jr]; vy += vb[jr + 1];
                }
                uint32_t h, l;
                split2(vx, vy, h, l);
                *(uint32_t*)(dhi + rb + dd) = h;
                *(uint32_t*)(dlo + rb + dd) = l;
            }
        }
}

// ---------------------------------------------------------------------------
// Kernel 2: windowed attention via split-bf16 mma.sync.
// One CTA per (window, head); 7 warps x 32 query rows (MP=224).
// 13 key tiles of 16 (NP=208), online softmax, P.V with ldmatrix.trans.
// ---------------------------------------------------------------------------
__global__ __launch_bounds__(224, 1) void k_attn_mma(const float* __restrict__ table)
{
    extern __shared__ char sm[];
    const uint32_t smb = smem_u32(sm);
    float* tbs = (float*)(sm + A_TB);
    const int w = blockIdx.x, h = blockIdx.y;
    const int tid = threadIdx.x;
    const int lane = tid & 31, wid = tid >> 5;   // wid 0..6
    const int lr = lane & 15, lh = lane >> 4;

    // --- cooperative load of Q/K/V hi+lo into swizzled smem ---
    {
        const long qb = ((long)w * NHD + h) * MP * HD;
        const long kb = ((long)w * NHD + h) * NP * HD;
        for (int idx = tid; idx < MP * 8; idx += 224) {
            const int row = idx >> 3, c = idx & 7;
            const uint32_t off = row * 128 + ((c ^ (row & 7)) << 4);
            const long go = qb + row * 64 + c * 8;
            cp16(smb + A_QHI + off, g_qhi + go);
            cp16(smb + A_QLO + off, g_qlo + go);
        }
        for (int idx = tid; idx < NP * 8; idx += 224) {
            const int row = idx >> 3, c = idx & 7;
            const uint32_t off = row * 128 + ((c ^ (row & 7)) << 4);
            const long go = kb + row * 64 + c * 8;
            cp16(smb + A_KHI + off, g_khi + go);
            cp16(smb + A_KLO + off, g_klo + go);
            cp16(smb + A_VHI + off, g_vhi + go);
            cp16(smb + A_VLO + off, g_vlo + go);
        }
        cp_commit();
        for (int t = tid; t < 729; t += 224) tbs[t] = table[t * NHD + h];
        cp_wait0();
    }
    __syncthreads();

    // --- preload Q fragments (rows wid*32 .. +31) ---
    uint32_t qfh[2][4][4], qfl[2][4][4];
#pragma unroll
    for (int mf = 0; mf < 2; mf++)
#pragma unroll
        for (int s = 0; s < 4; s++) {
            const int row = wid * 32 + mf * 16 + lr;
            const uint32_t off = row * 128 + (((2 * s + lh) ^ (row & 7)) << 4);
            ldsm4(qfh[mf][s], smb + A_QHI + off);
            ldsm4(qfl[mf][s], smb + A_QLO + off);
        }

    // --- per-thread row info (4 rows: [mf][rh]) ---
    int rbias[2][2];
    bool rok[2][2];
    const int g = lane >> 2;
#pragma unroll
    for (int mf = 0; mf < 2; mf++)
#pragma unroll
        for (int rh = 0; rh < 2; rh++) {
            const int r = wid * 32 + mf * 16 + rh * 8 + g;
            rok[mf][rh] = (r < NT);
            const int iy = r / WSZ, ix = r - (r / WSZ) * WSZ;
            rbias[mf][rh] = iy * 27 + ix + 13 * 28;
        }

    float mM[2][2], lL[2][2];
    float o[2][8][4];
#pragma unroll
    for (int mf = 0; mf < 2; mf++)
#pragma unroll
        for (int rh = 0; rh < 2; rh++) { mM[mf][rh] = -1e30f; lL[mf][rh] = 0.f; }
#pragma unroll
    for (int a = 0; a < 2; a++)
#pragma unroll
        for (int b = 0; b < 8; b++)
#pragma unroll
            for (int c = 0; c < 4; c++) o[a][b][c] = 0.f;

    const int cbase = 2 * (lane & 3);

    for (int it = 0; it < 13; it++) {
        // K fragments for this 16-key tile.
        uint32_t kfh[4][4], kfl[4][4];
#pragma unroll
        for (int s = 0; s < 4; s++) {
            const int row = it * 16 + lr;
            const uint32_t off = row * 128 + (((2 * s + lh) ^ (row & 7)) << 4);
            ldsm4(kfh[s], smb + A_KHI + off);
            ldsm4(kfl[s], smb + A_KLO + off);
        }
        // S = Q K^T (3-term split), fp32 accum.
        float sc[2][2][4];
#pragma unroll
        for (int mf = 0; mf < 2; mf++)
#pragma unroll
            for (int q = 0; q < 2; q++)
#pragma unroll
                for (int e = 0; e < 4; e++) sc[mf][q][e] = 0.f;
#pragma unroll
        for (int s = 0; s < 4; s++)
#pragma unroll
            for (int q = 0; q < 2; q++)
#pragma unroll
                for (int mf = 0; mf < 2; mf++) {
                    float* d = sc[mf][q];
                    mma16816(d, qfh[mf][s], kfh[s][q], kfh[s][q + 2]);
                    mma16816(d, qfh[mf][s], kfl[s][q], kfl[s][q + 2]);
                    mma16816(d, qfl[mf][s], kfh[s][q], kfh[s][q + 2]);
                }

        // Bias gather + mask.
        int cidx[2][2];
        bool cok[2][2];
#pragma unroll
        for (int q = 0; q < 2; q++)
#pragma unroll
            for (int e1 = 0; e1 < 2; e1++) {
                const int c = it * 16 + q * 8 + cbase + e1;
                cok[q][e1] = (c < NT);
                const int jy = c / WSZ;
                cidx[q][e1] = jy * 27 + (c - jy * WSZ);
            }
#pragma unroll
        for (int mf = 0; mf < 2; mf++)
#pragma unroll
            for (int q = 0; q < 2; q++)
#pragma unroll
                for (int e = 0; e < 4; e++) {
                    const int rh = e >> 1, e1 = e & 1;
                    if (!cok[q][e1]) sc[mf][q][e] = -1e30f;
                    else if (rok[mf][rh])
                        sc[mf][q][e] += tbs[rbias[mf][rh] - cidx[q][e1]];
                }

        // Online softmax per row group.
#pragma unroll
        for (int mf = 0; mf < 2; mf++)
#pragma unroll
            for (int rh = 0; rh < 2; rh++) {
                float vmax = fmaxf(fmaxf(sc[mf][0][2 * rh], sc[mf][0][2 * rh + 1]),
                                   fmaxf(sc[mf][1][2 * rh], sc[mf][1][2 * rh + 1]));
                vmax = fmaxf(vmax, __shfl_xor_sync(0xffffffffu, vmax, 1));
                vmax = fmaxf(vmax, __shfl_xor_sync(0xffffffffu, vmax, 2));
                const float mn = fmaxf(mM[mf][rh], vmax);
                const float corr = __expf(mM[mf][rh] - mn);
                mM[mf][rh] = mn;
                float rs = 0.f;
#pragma unroll
                for (int q = 0; q < 2; q++)
#pragma unroll
                    for (int e1 = 0; e1 < 2; e1++) {
                        const float p = __expf(sc[mf][q][2 * rh + e1] - mn);
                        sc[mf][q][2 * rh + e1] = p;
                        rs += p;
                    }
                rs += __shfl_xor_sync(0xffffffffu, rs, 1);
                rs += __shfl_xor_sync(0xffffffffu, rs, 2);
                lL[mf][rh] = lL[mf][rh] * corr + rs;
#pragma unroll
                for (int n = 0; n < 8; n++) {
                    o[mf][n][2 * rh + 0] *= corr;
                    o[mf][n][2 * rh + 1] *= corr;
                }
            }

        // P -> A-fragments (hi/lo).  C-frag(m16n16) == A-frag(m16k16).
        uint32_t pfh[2][4], pfl[2][4];
#pragma unroll
        for (int mf = 0; mf < 2; mf++) {
            split2(sc[mf][0][0], sc[mf][0][1], pfh[mf][0], pfl[mf][0]);
            split2(sc[mf][0][2], sc[mf][0][3], pfh[mf][1], pfl[mf][1]);
            split2(sc[mf][1][0], sc[mf][1][1], pfh[mf][2], pfl[mf][2]);
            split2(sc[mf][1][2], sc[mf][1][3], pfh[mf][3], pfl[mf][3]);
        }

        // O += P V (V via ldmatrix.trans; 3-term split).
#pragma unroll
        for (int gg = 0; gg < 4; gg++) {
            const int row = it * 16 + lr;
            const uint32_t off = row * 128 + (((2 * gg + lh) ^ (row & 7)) << 4);
            uint32_t vfh[4], vfl[4];
            ldsm4t(vfh, smb + A_VHI + off);
            ldsm4t(vfl, smb + A_VLO + off);
#pragma unroll
            for (int q = 0; q < 2; q++)
#pragma unroll
                for (int mf = 0; mf < 2; mf++) {
                    float* d = o[mf][gg * 2 + q];
                    mma16816(d, pfh[mf], vfh[2 * q], vfh[2 * q + 1]);
                    mma16816(d, pfh[mf], vfl[2 * q], vfl[2 * q + 1]);
                    mma16816(d, pfl[mf], vfh[2 * q], vfh[2 * q + 1]);
                }
        }
    }

    // Epilogue: divide by l, window-reverse, emit bf16 hi/lo for proj GEMM.
    const int bimg = w >> 4, wi = w & 15;
#pragma unroll
    for (int mf = 0; mf < 2; mf++)
#pragma unroll
        for (int rh = 0; rh < 2; rh++) {
            if (!rok[mf][rh]) continue;
            const int r = wid * 32 + mf * 16 + rh * 8 + g;
            const int iy = r / WSZ, ix = r - (r / WSZ) * WSZ;
            const int rr = (wi >> 2) * WSZ + iy;
            const int cc = (wi & 3) * WSZ + ix;
            const long ob = ((long)bimg * 3136 + (long)rr * 56 + cc) * CDIM + h * HD;
            const float inv = 1.f / lL[mf][rh];
#pragma unroll
            for (int n = 0; n < 8; n++) {
                const int col = n * 8 + cbase;
                uint32_t hh, ll;
                split2(o[mf][n][2 * rh] * inv, o[mf][n][2 * rh + 1] * inv, hh, ll);
                *(uint32_t*)(g_ahi + ob + col) = hh;
                *(uint32_t*)(g_alo + ob + col) = ll;
            }
        }
}

// ---------------------------------------------------------------------------
// Kernel 3: output projection GEMM (bf16 inputs from g_ahi/lo, g_pwhi/lo)
// ---------------------------------------------------------------------------
__global__ __launch_bounds__(256, 2) void k_proj_mma(
    const float* __restrict__ pb, float* __restrict__ out)
{
    extern __shared__ char sm[];
    const uint32_t smb = smem_u32(sm);
    const int tid = threadIdx.x;
    const int lane = tid & 31, wid = tid >> 5;
    const int bn = blockIdx.x, bm = blockIdx.y;
    const int m0 = bm * 128, n0 = bn * 128;

    const long aoff = (long)(m0 + (tid >> 1)) * CDIM;
    const long boff = (long)(n0 + (tid >> 1)) * CDIM;

    float acc[2][8][4];
#pragma unroll
    for (int a = 0; a < 2; a++)
#pragma unroll
        for (int b = 0; b < 8; b++)
#pragma unroll
            for (int c = 0; c < 4; c++) acc[a][b][c] = 0.f;

    gemm_main(smb, g_ahi + aoff, g_alo + aoff, g_pwhi + boff, g_pwlo + boff, acc);

    const int m_base = (wid & 3) * 32, n_base = (wid >> 2) * 64;
    const int qrow = lane >> 2, qcol = (lane & 3) * 2;

#pragma unroll
    for (int mf = 0; mf < 2; mf++)
#pragma unroll
        for (int half = 0; half < 2; half++) {
            const int rl = m_base + mf * 16 + half * 8 + qrow;
            const int m = m0 + rl;
            float* rp = out + (long)m * CDIM + n0 + n_base;
#pragma unroll
            for (int nf = 0; nf < 8; nf++) {
                const int dd = nf * 8 + qcol;
                const float2 bias = *(const float2*)(pb + n0 + n_base + dd);
                *(float2*)(rp + dd) = make_float2(
                    acc[mf][nf][half * 2 + 0] + bias.x,
                    acc[mf][nf][half * 2 + 1] + bias.y);
            }
        }
}

// ---------------------------------------------------------------------------
extern "C" void kernel_launch(void* const* d_in, const int* in_sizes, int n_in,
                              void* d_out, int out_size)
{
    const float* x    = (const float*)d_in[0];
    const float* qkvw = (const float*)d_in[1];
    const float* qb   = (const float*)d_in[2];
    const float* vb   = (const float*)d_in[3];
    const float* tbl  = (const float*)d_in[4];
    const float* pw   = (const float*)d_in[5];
    const float* pb   = (const float*)d_in[6];
    float* out = (float*)d_out;

    cudaFuncSetAttribute(k_qkv_mma,
                         cudaFuncAttributeMaxDynamicSharedMemorySize, SMEM_TOT);
    cudaFuncSetAttribute(k_proj_mma,
                         cudaFuncAttributeMaxDynamicSharedMemorySize, SMEM_TOT);
    cudaFuncSetAttribute(k_attn_mma,
                         cudaFuncAttributeMaxDynamicSharedMemorySize, SMEM_ATT);

    __nv_bfloat16 *xhi, *xlo, *whi, *wlo, *pwhi, *pwlo;
    cudaGetSymbolAddress((void**)&xhi, g_xhi);
    cudaGetSymbolAddress((void**)&xlo, g_xlo);
    cudaGetSymbolAddress((void**)&whi, g_whi);
    cudaGetSymbolAddress((void**)&wlo, g_wlo);
    cudaGetSymbolAddress((void**)&pwhi, g_pwhi);
    cudaGetSymbolAddress((void**)&pwlo, g_pwlo);

    // Pre-convert fp32 operands to bf16 hi/lo.
    {
        const long n4x = (long)M1 * CDIM / 4;
        k_cvt<<<(unsigned)((n4x + 255) / 256), 256>>>(x, xhi, xlo, n4x);
        const long n4w = (long)QKVN * CDIM / 4;
        k_cvt<<<(unsigned)((n4w + 255) / 256), 256>>>(qkvw, whi, wlo, n4w);
        const long n4p = (long)CDIM * CDIM / 4;
        k_cvt<<<(unsigned)((n4p + 255) / 256), 256>>>(pw, pwhi, pwlo, n4p);
    }

    dim3 g1(QKVN / 128, M1 / 128);   // (18, 392)
    k_qkv_mma<<<g1, 256, SMEM_TOT>>>(qb, vb);

    dim3 g2(NWIN, NHD);              // (256, 12)
    k_attn_mma<<<g2, 224, SMEM_ATT>>>(tbl);

    dim3 g3(CDIM / 128, M1 / 128);   // (6, 392)
    k_proj_mma<<<g3, 256, SMEM_TOT>>>(pb, out);
}

// round 13
// speedup vs baseline: 1.8484x; 1.1693x over previous
#include <cuda_runtime.h>
#include <cuda_bf16.h>
#include <cstdint>

// Problem constants.
constexpr int CDIM = 768;
constexpr int NHD  = 12;
constexpr int HD   = 64;
constexpr int WSZ  = 14;
constexpr int NT   = WSZ * WSZ;        // 196
constexpr int NWIN = 256;
constexpr int M1   = NWIN * NT;        // 50176
constexpr int QKVN = 3 * CDIM;         // 2304

// Attention padded dims (mma tiles of 16).
constexpr int MP = 224;                // query rows padded (14 x 16)
constexpr int NP = 208;                // key rows padded (13 x 16)

// GEMM tiling: CTA 128x128, K-chunk 32, 8 warps (4Mx2N), 3 stages.
constexpr int KCH = 32;
constexpr int NCH = CDIM / KCH;        // 24
constexpr int T_AHI = 0;
constexpr int T_ALO = 8192;
constexpr int T_BHI = 16384;
constexpr int T_BLO = 24576;
constexpr int STG_B = 32768;
constexpr int MB_OFF = 3 * STG_B;      // 6 mbarriers after the stages
constexpr int SMEM_TOT = MB_OFF + 64;  // 96 KB + 64

// Attention smem layout (bytes).
constexpr int A_QHI = 0;
constexpr int A_QLO = A_QHI + MP * 128;    // 28672
constexpr int A_KHI = A_QLO + MP * 128;    // 57344
constexpr int A_KLO = A_KHI + NP * 128;    // 83968
constexpr int A_VHI = A_KLO + NP * 128;    // 110592
constexpr int A_VLO = A_VHI + NP * 128;    // 137216
constexpr int A_TB  = A_VLO + NP * 128;    // 163840
constexpr int SMEM_ATT = A_TB + 729 * 4 + 28;  // ~163 KB

// Scratch (device globals; runtime allocation is forbidden; BSS is zero-init,
// so padded rows of q/k/v read as zeros).
__device__ __nv_bfloat16 g_qhi[(long)NWIN * NHD * MP * HD];
__device__ __nv_bfloat16 g_qlo[(long)NWIN * NHD * MP * HD];
__device__ __nv_bfloat16 g_khi[(long)NWIN * NHD * NP * HD];
__device__ __nv_bfloat16 g_klo[(long)NWIN * NHD * NP * HD];
__device__ __nv_bfloat16 g_vhi[(long)NWIN * NHD * NP * HD];
__device__ __nv_bfloat16 g_vlo[(long)NWIN * NHD * NP * HD];
__device__ __nv_bfloat16 g_xhi[(long)M1 * CDIM];
__device__ __nv_bfloat16 g_xlo[(long)M1 * CDIM];
__device__ __nv_bfloat16 g_whi[(long)QKVN * CDIM];
__device__ __nv_bfloat16 g_wlo[(long)QKVN * CDIM];
__device__ __nv_bfloat16 g_pwhi[(long)CDIM * CDIM];
__device__ __nv_bfloat16 g_pwlo[(long)CDIM * CDIM];
__device__ __nv_bfloat16 g_ahi[(long)M1 * CDIM];
__device__ __nv_bfloat16 g_alo[(long)M1 * CDIM];

// ---------------------------------------------------------------------------
// PTX helpers (base-target instructions only; tcgen05 is rejected by ptxas
// on the harness's compute_103 virtual target).
// ---------------------------------------------------------------------------
__device__ __forceinline__ uint32_t smem_u32(const void* p) {
    uint32_t a;
    asm("{ .reg .u64 t; cvta.to.shared.u64 t, %1; cvt.u32.u64 %0, t; }"
        : "=r"(a) : "l"(p));
    return a;
}
__device__ __forceinline__ void cp16(uint32_t dst, const void* src) {
    asm volatile("cp.async.cg.shared.global [%0], [%1], 16;"
                 :: "r"(dst), "l"(src));
}
__device__ __forceinline__ void cp_commit() {
    asm volatile("cp.async.commit_group;");
}
__device__ __forceinline__ void cp_wait0() {
    asm volatile("cp.async.wait_group 0;" ::: "memory");
}
__device__ __forceinline__ void mbar_init(uint32_t a, uint32_t cnt) {
    asm volatile("mbarrier.init.shared.b64 [%0], %1;" :: "r"(a), "r"(cnt) : "memory");
}
__device__ __forceinline__ void mbar_arrive(uint32_t a) {
    asm volatile("mbarrier.arrive.shared.b64 _, [%0];" :: "r"(a) : "memory");
}
// .noinc is load-bearing: the async completion's arrival must count against
// the init()-time expected count. The default (incrementing) form is
// self-balancing and would never complete the phase -> CTA-wide hang
// (root cause of the R11/R12 container timeouts).
__device__ __forceinline__ void cp_arrive(uint32_t a) {
    asm volatile("cp.async.mbarrier.arrive.noinc.shared.b64 [%0];" :: "r"(a) : "memory");
}
__device__ __forceinline__ void mbar_wait(uint32_t a, uint32_t par) {
    asm volatile(
        "{\n\t.reg .pred P1;\n\t"
        "WL_%=:\n\t"
        "mbarrier.try_wait.parity.acquire.cta.shared::cta.b64 P1, [%0], %1, 0x989680;\n\t"
        "@P1 bra.uni WD_%=;\n\t"
        "bra.uni WL_%=;\n\t"
        "WD_%=:\n\t}"
        :: "r"(a), "r"(par) : "memory");
}
__device__ __forceinline__ void ldsm4(uint32_t* r, uint32_t addr) {
    asm volatile("ldmatrix.sync.aligned.m8n8.x4.shared.b16 {%0,%1,%2,%3}, [%4];"
                 : "=r"(r[0]), "=r"(r[1]), "=r"(r[2]), "=r"(r[3]) : "r"(addr));
}
__device__ __forceinline__ void ldsm4t(uint32_t* r, uint32_t addr) {
    asm volatile("ldmatrix.sync.aligned.m8n8.x4.trans.shared.b16 {%0,%1,%2,%3}, [%4];"
                 : "=r"(r[0]), "=r"(r[1]), "=r"(r[2]), "=r"(r[3]) : "r"(addr));
}
__device__ __forceinline__ void mma16816(float* d, const uint32_t* a,
                                         uint32_t b0, uint32_t b1) {
    asm volatile(
        "mma.sync.aligned.m16n8k16.row.col.f32.bf16.bf16.f32 "
        "{%0,%1,%2,%3}, {%4,%5,%6,%7}, {%8,%9}, {%0,%1,%2,%3};"
        : "+f"(d[0]), "+f"(d[1]), "+f"(d[2]), "+f"(d[3])
        : "r"(a[0]), "r"(a[1]), "r"(a[2]), "r"(a[3]), "r"(b0), "r"(b1));
}

// 2 floats -> bf16x2 hi + bf16x2 lo words.
__device__ __forceinline__ void split2(float x, float y, uint32_t& h, uint32_t& l) {
    __nv_bfloat162 hh = __floats2bfloat162_rn(x, y);
    float2 f = __bfloat1622float2(hh);
    __nv_bfloat162 ll = __floats2bfloat162_rn(x - f.x, y - f.y);
    h = *(uint32_t*)&hh; l = *(uint32_t*)&ll;
}
// 4 floats -> bf16 hi (8B) + bf16 lo (8B).
__device__ __forceinline__ void split4(float4 v, uint2& hi, uint2& lo) {
    split2(v.x, v.y, hi.x, lo.x);
    split2(v.z, v.w, hi.y, lo.y);
}

// ---------------------------------------------------------------------------
// Kernel 0: fp32 -> bf16 hi/lo conversion (elementwise).
// ---------------------------------------------------------------------------
__global__ __launch_bounds__(256) void k_cvt(const float* __restrict__ src,
                                            __nv_bfloat16* __restrict__ hi,
                                            __nv_bfloat16* __restrict__ lo,
                                            long n4)
{
    const long i = (long)blockIdx.x * blockDim.x + threadIdx.x;
    if (i >= n4) return;
    float4 v = *(const float4*)(src + i * 4);
    uint2 h, l;
    split4(v, h, l);
    *(uint2*)(hi + i * 4) = h;
    *(uint2*)(lo + i * 4) = l;
}

// ---------------------------------------------------------------------------
// Shared bf16 GEMM mainloop: CTA 128x128, warp 32x64, 3 stages, mbarrier-
// gated pipeline (fill: 256 noinc cp-completion arrivals; free: 8 post-ldsm
// warp arrivals) so one warp's MMA tail never blocks the others.
// ---------------------------------------------------------------------------
__device__ __forceinline__ void gemm_main(uint32_t smb,
                                          const __nv_bfloat16* aHiR,
                                          const __nv_bfloat16* aLoR,
                                          const __nv_bfloat16* bHiR,
                                          const __nv_bfloat16* bLoR,
                                          float acc[2][8][4]) {
    const int tid = threadIdx.x;
    const int lane = tid & 31, wid = tid >> 5;
    const int srow = tid >> 1, shalf = tid & 1;
    const int bswz = (srow >> 1) & 3;

    const uint32_t FILL = smb + MB_OFF;        // 3 x 8B
    const uint32_t FREE = smb + MB_OFF + 24;   // 3 x 8B
    if (tid == 0) {
#pragma unroll
        for (int s = 0; s < 3; s++) {
            mbar_init(FILL + 8 * s, 256);
            mbar_init(FREE + 8 * s, 8);
        }
    }
    __syncthreads();

    const uint32_t d0 = srow * 64 + (((shalf * 2 + 0) ^ bswz) * 16);
    const uint32_t d1 = srow * 64 + (((shalf * 2 + 1) ^ bswz) * 16);
    const int e0 = (shalf * 2 + 0) * 8;
    const int e1 = (shalf * 2 + 1) * 8;

    auto issue = [&](int c) {
        const int t = c % 3;
        const uint32_t st = smb + t * STG_B;
        const int kb = c * KCH;
        cp16(st + T_AHI + d0, aHiR + kb + e0);
        cp16(st + T_AHI + d1, aHiR + kb + e1);
        cp16(st + T_ALO + d0, aLoR + kb + e0);
        cp16(st + T_ALO + d1, aLoR + kb + e1);
        cp16(st + T_BHI + d0, bHiR + kb + e0);
        cp16(st + T_BHI + d1, bHiR + kb + e1);
        cp16(st + T_BLO + d0, bLoR + kb + e0);
        cp16(st + T_BLO + d1, bLoR + kb + e1);
        cp_arrive(FILL + 8 * t);
    };

    const int m_base = (wid & 3) * 32;
    const int n_base = (wid >> 2) * 64;
    const int lr = lane & 15, lh = lane >> 4;
    const int rA = m_base + lr;
    const int rB = n_base + lr;
    const uint32_t swA = (rA >> 1) & 3;
    const uint32_t swB = (rB >> 1) & 3;
    const uint32_t paS[2] = {((0 + lh) ^ swA) * 16, ((2 + lh) ^ swA) * 16};
    const uint32_t pbS[2] = {((0 + lh) ^ swB) * 16, ((2 + lh) ^ swB) * 16};
    const uint32_t rA64 = rA * 64, rB64 = rB * 64;

    issue(0);
    issue(1);
    for (int c = 0; c < NCH; c++) {
        const int s = c % 3;
        const int u = c / 3;
        mbar_wait(FILL + 8 * s, (uint32_t)(u & 1));

        const uint32_t st = smb + s * STG_B;
        const uint32_t aHi = st + T_AHI + rA64;
        const uint32_t aLo = st + T_ALO + rA64;
        const uint32_t bHi = st + T_BHI + rB64;
        const uint32_t bLo = st + T_BLO + rB64;

#pragma unroll
        for (int ks = 0; ks < 2; ks++) {
            const uint32_t pa = paS[ks], pb = pbS[ks];
            uint32_t ah[2][4], al[2][4];
            ldsm4(ah[0], aHi + pa); ldsm4(ah[1], aHi + 1024 + pa);
            ldsm4(al[0], aLo + pa); ldsm4(al[1], aLo + 1024 + pa);
            uint32_t bh[4][4], bl[4][4];
#pragma unroll
            for (int nfp = 0; nfp < 4; nfp++) {
                ldsm4(bh[nfp], bHi + nfp * 1024 + pb);
                ldsm4(bl[nfp], bLo + nfp * 1024 + pb);
            }
            if (ks == 1) {
                // All ldsm reads of this stage are done: free it, then
                // (after all warps freed it) refill with chunk c+2.
                if (lane == 0) mbar_arrive(FREE + 8 * s);
                if (c + 2 < NCH) {
                    const int t = (c + 2) % 3;
                    const int v = (c + 2) / 3;
                    if (v > 0) mbar_wait(FREE + 8 * t, (uint32_t)((v - 1) & 1));
                    issue(c + 2);
                }
            }
#pragma unroll
            for (int nfp = 0; nfp < 4; nfp++)
#pragma unroll
                for (int mf = 0; mf < 2; mf++)
#pragma unroll
                    for (int q = 0; q < 2; q++) {
                        float* d = acc[mf][nfp * 2 + q];
                        mma16816(d, ah[mf], bh[nfp][q], bh[nfp][q + 2]); // hi*hi
                        mma16816(d, ah[mf], bl[nfp][q], bl[nfp][q + 2]); // hi*lo
                        mma16816(d, al[mf], bh[nfp][q], bh[nfp][q + 2]); // lo*hi
                    }
        }
    }
}

// ---------------------------------------------------------------------------
// Kernel 1: fused window-partition + QKV GEMM; epilogue writes q/k/v as
// bf16 hi/lo into padded per-(window,head) layouts for the mma attention.
// ---------------------------------------------------------------------------
__global__ __launch_bounds__(256, 2) void k_qkv_mma(
    const float* __restrict__ qb, const float* __restrict__ vb)
{
    extern __shared__ char sm[];
    const uint32_t smb = smem_u32(sm);
    const int tid = threadIdx.x;
    const int lane = tid & 31, wid = tid >> 5;
    const int bn = blockIdx.x, bm = blockIdx.y;
    const int m0 = bm * 128, n0 = bn * 128;

    long aoff;
    {
        const int srow = tid >> 1;
        const int am = m0 + srow;
        const int wwin = am / NT;
        const int nn = am - wwin * NT;
        const int bimg = wwin >> 4, wi = wwin & 15;
        const int rr = (wi >> 2) * WSZ + nn / WSZ;
        const int cc = (wi & 3) * WSZ + nn % WSZ;
        aoff = ((long)bimg * 3136 + (long)rr * 56 + cc) * CDIM;
    }
    const long boff = (long)(n0 + (tid >> 1)) * CDIM;

    float acc[2][8][4];
#pragma unroll
    for (int a = 0; a < 2; a++)
#pragma unroll
        for (int b = 0; b < 8; b++)
#pragma unroll
            for (int c = 0; c < 4; c++) acc[a][b][c] = 0.f;

    gemm_main(smb, g_xhi + aoff, g_xlo + aoff, g_whi + boff, g_wlo + boff, acc);

    // Epilogue: split-bf16 scatter into padded q/k/v.
    const int m_base = (wid & 3) * 32, n_base = (wid >> 2) * 64;
    const int qrow = lane >> 2, qcol = (lane & 3) * 2;
    const int part = n0 / CDIM;              // 0:q 1:k 2:v
    const int jrbase = n0 - part * CDIM + n_base;
    const int hh = jrbase >> 6;
    __nv_bfloat16* dhi = (part == 0) ? g_qhi : (part == 1) ? g_khi : g_vhi;
    __nv_bfloat16* dlo = (part == 0) ? g_qlo : (part == 1) ? g_klo : g_vlo;
    const int rstr = (part == 0) ? MP : NP;

#pragma unroll
    for (int mf = 0; mf < 2; mf++)
#pragma unroll
        for (int half = 0; half < 2; half++) {
            const int rl = m_base + mf * 16 + half * 8 + qrow;
            const int m = m0 + rl;
            const int w2 = m / NT, n2 = m - w2 * NT;
            const long rb = (((long)w2 * NHD + hh) * rstr + n2) * HD;
#pragma unroll
            for (int nf = 0; nf < 8; nf++) {
                const int dd = nf * 8 + qcol;
                float vx = acc[mf][nf][half * 2 + 0];
                float vy = acc[mf][nf][half * 2 + 1];
                const int jr = jrbase + dd;
                if (part == 0) {
                    vx = (vx + qb[jr]) * 0.125f;
                    vy = (vy + qb[jr + 1]) * 0.125f;
                } else if (part == 2) {
                    vx += vb[jr]; vy += vb[jr + 1];
                }
                uint32_t h, l;
                split2(vx, vy, h, l);
                *(uint32_t*)(dhi + rb + dd) = h;
                *(uint32_t*)(dlo + rb + dd) = l;
            }
        }
}

// ---------------------------------------------------------------------------
// Kernel 2: windowed attention via split-bf16 mma.sync (unchanged from R10).
// ---------------------------------------------------------------------------
__global__ __launch_bounds__(224, 1) void k_attn_mma(const float* __restrict__ table)
{
    extern __shared__ char sm[];
    const uint32_t smb = smem_u32(sm);
    float* tbs = (float*)(sm + A_TB);
    const int w = blockIdx.x, h = blockIdx.y;
    const int tid = threadIdx.x;
    const int lane = tid & 31, wid = tid >> 5;   // wid 0..6
    const int lr = lane & 15, lh = lane >> 4;

    // --- cooperative load of Q/K/V hi+lo into swizzled smem ---
    {
        const long qb = ((long)w * NHD + h) * MP * HD;
        const long kb = ((long)w * NHD + h) * NP * HD;
        for (int idx = tid; idx < MP * 8; idx += 224) {
            const int row = idx >> 3, c = idx & 7;
            const uint32_t off = row * 128 + ((c ^ (row & 7)) << 4);
            const long go = qb + row * 64 + c * 8;
            cp16(smb + A_QHI + off, g_qhi + go);
            cp16(smb + A_QLO + off, g_qlo + go);
        }
        for (int idx = tid; idx < NP * 8; idx += 224) {
            const int row = idx >> 3, c = idx & 7;
            const uint32_t off = row * 128 + ((c ^ (row & 7)) << 4);
            const long go = kb + row * 64 + c * 8;
            cp16(smb + A_KHI + off, g_khi + go);
            cp16(smb + A_KLO + off, g_klo + go);
            cp16(smb + A_VHI + off, g_vhi + go);
            cp16(smb + A_VLO + off, g_vlo + go);
        }
        cp_commit();
        for (int t = tid; t < 729; t += 224) tbs[t] = table[t * NHD + h];
        cp_wait0();
    }
    __syncthreads();

    // --- preload Q fragments (rows wid*32 .. +31) ---
    uint32_t qfh[2][4][4], qfl[2][4][4];
#pragma unroll
    for (int mf = 0; mf < 2; mf++)
#pragma unroll
        for (int s = 0; s < 4; s++) {
            const int row = wid * 32 + mf * 16 + lr;
            const uint32_t off = row * 128 + (((2 * s + lh) ^ (row & 7)) << 4);
            ldsm4(qfh[mf][s], smb + A_QHI + off);
            ldsm4(qfl[mf][s], smb + A_QLO + off);
        }

    // --- per-thread row info (4 rows: [mf][rh]) ---
    int rbias[2][2];
    bool rok[2][2];
    const int g = lane >> 2;
#pragma unroll
    for (int mf = 0; mf < 2; mf++)
#pragma unroll
        for (int rh = 0; rh < 2; rh++) {
            const int r = wid * 32 + mf * 16 + rh * 8 + g;
            rok[mf][rh] = (r < NT);
            const int iy = r / WSZ, ix = r - (r / WSZ) * WSZ;
            rbias[mf][rh] = iy * 27 + ix + 13 * 28;
        }

    float mM[2][2], lL[2][2];
    float o[2][8][4];
#pragma unroll
    for (int mf = 0; mf < 2; mf++)
#pragma unroll
        for (int rh = 0; rh < 2; rh++) { mM[mf][rh] = -1e30f; lL[mf][rh] = 0.f; }
#pragma unroll
    for (int a = 0; a < 2; a++)
#pragma unroll
        for (int b = 0; b < 8; b++)
#pragma unroll
            for (int c = 0; c < 4; c++) o[a][b][c] = 0.f;

    const int cbase = 2 * (lane & 3);

    for (int it = 0; it < 13; it++) {
        // K fragments for this 16-key tile.
        uint32_t kfh[4][4], kfl[4][4];
#pragma unroll
        for (int s = 0; s < 4; s++) {
            const int row = it * 16 + lr;
            const uint32_t off = row * 128 + (((2 * s + lh) ^ (row & 7)) << 4);
            ldsm4(kfh[s], smb + A_KHI + off);
            ldsm4(kfl[s], smb + A_KLO + off);
        }
        // S = Q K^T (3-term split), fp32 accum.
        float sc[2][2][4];
#pragma unroll
        for (int mf = 0; mf < 2; mf++)
#pragma unroll
            for (int q = 0; q < 2; q++)
#pragma unroll
                for (int e = 0; e < 4; e++) sc[mf][q][e] = 0.f;
#pragma unroll
        for (int s = 0; s < 4; s++)
#pragma unroll
            for (int q = 0; q < 2; q++)
#pragma unroll
                for (int mf = 0; mf < 2; mf++) {
                    float* d = sc[mf][q];
                    mma16816(d, qfh[mf][s], kfh[s][q], kfh[s][q + 2]);
                    mma16816(d, qfh[mf][s], kfl[s][q], kfl[s][q + 2]);
                    mma16816(d, qfl[mf][s], kfh[s][q], kfh[s][q + 2]);
                }

        // Bias gather + mask.
        int cidx[2][2];
        bool cok[2][2];
#pragma unroll
        for (int q = 0; q < 2; q++)
#pragma unroll
            for (int e1 = 0; e1 < 2; e1++) {
                const int c = it * 16 + q * 8 + cbase + e1;
                cok[q][e1] = (c < NT);
                const int jy = c / WSZ;
                cidx[q][e1] = jy * 27 + (c - jy * WSZ);
            }
#pragma unroll
        for (int mf = 0; mf < 2; mf++)
#pragma unroll
            for (int q = 0; q < 2; q++)
#pragma unroll
                for (int e = 0; e < 4; e++) {
                    const int rh = e >> 1, e1 = e & 1;
                    if (!cok[q][e1]) sc[mf][q][e] = -1e30f;
                    else if (rok[mf][rh])
                        sc[mf][q][e] += tbs[rbias[mf][rh] - cidx[q][e1]];
                }

        // Online softmax per row group.
#pragma unroll
        for (int mf = 0; mf < 2; mf++)
#pragma unroll
            for (int rh = 0; rh < 2; rh++) {
                float vmax = fmaxf(fmaxf(sc[mf][0][2 * rh], sc[mf][0][2 * rh + 1]),
                                   fmaxf(sc[mf][1][2 * rh], sc[mf][1][2 * rh + 1]));
                vmax = fmaxf(vmax, __shfl_xor_sync(0xffffffffu, vmax, 1));
                vmax = fmaxf(vmax, __shfl_xor_sync(0xffffffffu, vmax, 2));
                const float mn = fmaxf(mM[mf][rh], vmax);
                const float corr = __expf(mM[mf][rh] - mn);
                mM[mf][rh] = mn;
                float rs = 0.f;
#pragma unroll
                for (int q = 0; q < 2; q++)
#pragma unroll
                    for (int e1 = 0; e1 < 2; e1++) {
                        const float p = __expf(sc[mf][q][2 * rh + e1] - mn);
                        sc[mf][q][2 * rh + e1] = p;
                        rs += p;
                    }
                rs += __shfl_xor_sync(0xffffffffu, rs, 1);
                rs += __shfl_xor_sync(0xffffffffu, rs, 2);
                lL[mf][rh] = lL[mf][rh] * corr + rs;
#pragma unroll
                for (int n = 0; n < 8; n++) {
                    o[mf][n][2 * rh + 0] *= corr;
                    o[mf][n][2 * rh + 1] *= corr;
                }
            }

        // P -> A-fragments (hi/lo).  C-frag(m16n16) == A-frag(m16k16).
        uint32_t pfh[2][4], pfl[2][4];
#pragma unroll
        for (int mf = 0; mf < 2; mf++) {
            split2(sc[mf][0][0], sc[mf][0][1], pfh[mf][0], pfl[mf][0]);
            split2(sc[mf][0][2], sc[mf][0][3], pfh[mf][1], pfl[mf][1]);
            split2(sc[mf][1][0], sc[mf][1][1], pfh[mf][2], pfl[mf][2]);
            split2(sc[mf][1][2], sc[mf][1][3], pfh[mf][3], pfl[mf][3]);
        }

        // O += P V (V via ldmatrix.trans; 3-term split).
#pragma unroll
        for (int gg = 0; gg < 4; gg++) {
            const int row = it * 16 + lr;
            const uint32_t off = row * 128 + (((2 * gg + lh) ^ (row & 7)) << 4);
            uint32_t vfh[4], vfl[4];
            ldsm4t(vfh, smb + A_VHI + off);
            ldsm4t(vfl, smb + A_VLO + off);
#pragma unroll
            for (int q = 0; q < 2; q++)
#pragma unroll
                for (int mf = 0; mf < 2; mf++) {
                    float* d = o[mf][gg * 2 + q];
                    mma16816(d, pfh[mf], vfh[2 * q], vfh[2 * q + 1]);
                    mma16816(d, pfh[mf], vfl[2 * q], vfl[2 * q + 1]);
                    mma16816(d, pfl[mf], vfh[2 * q], vfh[2 * q + 1]);
                }
        }
    }

    // Epilogue: divide by l, window-reverse, emit bf16 hi/lo for proj GEMM.
    const int bimg = w >> 4, wi = w & 15;
#pragma unroll
    for (int mf = 0; mf < 2; mf++)
#pragma unroll
        for (int rh = 0; rh < 2; rh++) {
            if (!rok[mf][rh]) continue;
            const int r = wid * 32 + mf * 16 + rh * 8 + g;
            const int iy = r / WSZ, ix = r - (r / WSZ) * WSZ;
            const int rr = (wi >> 2) * WSZ + iy;
            const int cc = (wi & 3) * WSZ + ix;
            const long ob = ((long)bimg * 3136 + (long)rr * 56 + cc) * CDIM + h * HD;
            const float inv = 1.f / lL[mf][rh];
#pragma unroll
            for (int n = 0; n < 8; n++) {
                const int col = n * 8 + cbase;
                uint32_t hh, ll;
                split2(o[mf][n][2 * rh] * inv, o[mf][n][2 * rh + 1] * inv, hh, ll);
                *(uint32_t*)(g_ahi + ob + col) = hh;
                *(uint32_t*)(g_alo + ob + col) = ll;
            }
        }
}

// ---------------------------------------------------------------------------
// Kernel 3: output projection GEMM (bf16 inputs from g_ahi/lo, g_pwhi/lo)
// ---------------------------------------------------------------------------
__global__ __launch_bounds__(256, 2) void k_proj_mma(
    const float* __restrict__ pb, float* __restrict__ out)
{
    extern __shared__ char sm[];
    const uint32_t smb = smem_u32(sm);
    const int tid = threadIdx.x;
    const int lane = tid & 31, wid = tid >> 5;
    const int bn = blockIdx.x, bm = blockIdx.y;
    const int m0 = bm * 128, n0 = bn * 128;

    const long aoff = (long)(m0 + (tid >> 1)) * CDIM;
    const long boff = (long)(n0 + (tid >> 1)) * CDIM;

    float acc[2][8][4];
#pragma unroll
    for (int a = 0; a < 2; a++)
#pragma unroll
        for (int b = 0; b < 8; b++)
#pragma unroll
            for (int c = 0; c < 4; c++) acc[a][b][c] = 0.f;

    gemm_main(smb, g_ahi + aoff, g_alo + aoff, g_pwhi + boff, g_pwlo + boff, acc);

    const int m_base = (wid & 3) * 32, n_base = (wid >> 2) * 64;
    const int qrow = lane >> 2, qcol = (lane & 3) * 2;

#pragma unroll
    for (int mf = 0; mf < 2; mf++)
#pragma unroll
        for (int half = 0; half < 2; half++) {
            const int rl = m_base + mf * 16 + half * 8 + qrow;
            const int m = m0 + rl;
            float* rp = out + (long)m * CDIM + n0 + n_base;
#pragma unroll
            for (int nf = 0; nf < 8; nf++) {
                const int dd = nf * 8 + qcol;
                const float2 bias = *(const float2*)(pb + n0 + n_base + dd);
                *(float2*)(rp + dd) = make_float2(
                    acc[mf][nf][half * 2 + 0] + bias.x,
                    acc[mf][nf][half * 2 + 1] + bias.y);
            }
        }
}

// ---------------------------------------------------------------------------
extern "C" void kernel_launch(void* const* d_in, const int* in_sizes, int n_in,
                              void* d_out, int out_size)
{
    const float* x    = (const float*)d_in[0];
    const float* qkvw = (const float*)d_in[1];
    const float* qb   = (const float*)d_in[2];
    const float* vb   = (const float*)d_in[3];
    const float* tbl  = (const float*)d_in[4];
    const float* pw   = (const float*)d_in[5];
    const float* pb   = (const float*)d_in[6];
    float* out = (float*)d_out;

    cudaFuncSetAttribute(k_qkv_mma,
                         cudaFuncAttributeMaxDynamicSharedMemorySize, SMEM_TOT);
    cudaFuncSetAttribute(k_proj_mma,
                         cudaFuncAttributeMaxDynamicSharedMemorySize, SMEM_TOT);
    cudaFuncSetAttribute(k_attn_mma,
                         cudaFuncAttributeMaxDynamicSharedMemorySize, SMEM_ATT);

    __nv_bfloat16 *xhi, *xlo, *whi, *wlo, *pwhi, *pwlo;
    cudaGetSymbolAddress((void**)&xhi, g_xhi);
    cudaGetSymbolAddress((void**)&xlo, g_xlo);
    cudaGetSymbolAddress((void**)&whi, g_whi);
    cudaGetSymbolAddress((void**)&wlo, g_wlo);
    cudaGetSymbolAddress((void**)&pwhi, g_pwhi);
    cudaGetSymbolAddress((void**)&pwlo, g_pwlo);

    // Pre-convert fp32 operands to bf16 hi/lo.
    {
        const long n4x = (long)M1 * CDIM / 4;
        k_cvt<<<(unsigned)((n4x + 255) / 256), 256>>>(x, xhi, xlo, n4x);
        const long n4w = (long)QKVN * CDIM / 4;
        k_cvt<<<(unsigned)((n4w + 255) / 256), 256>>>(qkvw, whi, wlo, n4w);
        const long n4p = (long)CDIM * CDIM / 4;
        k_cvt<<<(unsigned)((n4p + 255) / 256), 256>>>(pw, pwhi, pwlo, n4p);
    }

    dim3 g1(QKVN / 128, M1 / 128);   // (18, 392)
    k_qkv_mma<<<g1, 256, SMEM_TOT>>>(qb, vb);

    dim3 g2(NWIN, NHD);              // (256, 12)
    k_attn_mma<<<g2, 224, SMEM_ATT>>>(tbl);

    dim3 g3(CDIM / 128, M1 / 128);   // (6, 392)
    k_proj_mma<<<g3, 256, SMEM_TOT>>>(pb, out);
}